// round 10
// baseline (speedup 1.0000x reference)
#include <cuda_runtime.h>
#include <math.h>

#define N_ANCH   172032
#define MAX_OUT  200
#define NMS_TH   0.4f
#define THRF     2.5f          // fixed compaction threshold; exactness-safe (prefix argument)
#define CAP      4096
#define M        512

// ---------------- static device scratch ----------------
__device__ unsigned g_ncand;                 // BSS-zero; snapshot+reset by mega each run
__device__ unsigned long long g_ckey[CAP];
__device__ float    g_scores[N_ANCH];        // exact path only (single-block use)

// ---------------- decode helper (matches reference _decode) ----------------
__device__ __forceinline__ void decode_box(const float4& rg, const float4& an,
                                           float& y1, float& x1, float& y2, float& x2,
                                           float& ar) {
    float dx = rg.x * 0.1f, dy = rg.y * 0.1f, dw = rg.z * 0.2f, dh = rg.w * 0.2f;
    float xc = dx * an.z + an.x;
    float yc = dy * an.w + an.y;
    float w  = expf(dw) * an.z;
    float h  = expf(dh) * an.w;
    y1 = yc - 0.5f * h;  x1 = xc - 0.5f * w;
    y2 = yc + 0.5f * h;  x2 = xc + 0.5f * w;
    ar = (y2 - y1) * (x2 - x1);
}

__device__ __forceinline__ float iou_f(float ay1, float ax1, float ay2, float ax2, float aar,
                                       float by1, float bx1, float by2, float bx2, float bar) {
    float ih = fmaxf(fminf(ay2, by2) - fmaxf(ay1, by1), 0.f);
    float iw = fmaxf(fminf(ax2, bx2) - fmaxf(ax1, bx1), 0.f);
    float inter = ih * iw;
    return inter / (aar + bar - inter + 1e-12f);
}

__device__ __forceinline__ void gather_one(int t, int idx, float m,
                                           const float4* __restrict__ reg4,
                                           const float*  __restrict__ lnd,
                                           const float4* __restrict__ anch4,
                                           float* __restrict__ out) {
    float4 rg = __ldg(reg4 + idx);
    float4 an = __ldg(anch4 + idx);
    float y1, x1, y2, x2, ar;
    decode_box(rg, an, y1, x1, y2, x2, ar);
    out[4 * t + 0] = y1 * m;
    out[4 * t + 1] = x1 * m;
    out[4 * t + 2] = y2 * m;
    out[4 * t + 3] = x2 * m;
    const float* lp = lnd + 10 * idx;
    float* op = out + 4 * MAX_OUT + 10 * t;
#pragma unroll
    for (int k = 0; k < 5; k++) {
        float lx = lp[2 * k]     * 0.1f * an.z + an.x;
        float ly = lp[2 * k + 1] * 0.1f * an.w + an.y;
        op[2 * k]     = lx * m;
        op[2 * k + 1] = ly * m;
    }
}

// ---------------- kernel 1: compact candidates above fixed threshold ----------------
__global__ void compact_kernel(const float4* __restrict__ cls4, int n) {
    int nv = n >> 1;                          // one float4 = two (cls0,score) pairs
    int v = blockIdx.x * blockDim.x + threadIdx.x;
    if (v < nv) {
        float4 c = __ldg(cls4 + v);
        if (c.y > THRF) {
            unsigned u = __float_as_uint(c.y) ^ 0x80000000u;
            unsigned pos = atomicAdd(&g_ncand, 1u);
            if (pos < CAP)
                g_ckey[pos] = ((unsigned long long)u << 32) | (unsigned)(~(unsigned)(2 * v));
        }
        if (c.w > THRF) {
            unsigned u = __float_as_uint(c.w) ^ 0x80000000u;
            unsigned pos = atomicAdd(&g_ncand, 1u);
            if (pos < CAP)
                g_ckey[pos] = ((unsigned long long)u << 32) | (unsigned)(~(unsigned)(2 * v + 1));
        }
    }
    if ((n & 1) && v == 0) {                  // generality guard (n is even here)
        float s = ((const float*)cls4)[2 * (n - 1) + 1];
        if (s > THRF) {
            unsigned u = __float_as_uint(s) ^ 0x80000000u;
            unsigned pos = atomicAdd(&g_ncand, 1u);
            if (pos < CAP)
                g_ckey[pos] = ((unsigned long long)u << 32) | (unsigned)(~(unsigned)(n - 1));
        }
    }
}

// ---------------- kernel 2: single-block rank + pairs + greedy + gather ----------------
__global__ __launch_bounds__(1024) void mega_kernel(const float2* __restrict__ cls,
                                                    const float4* __restrict__ reg4,
                                                    const float*  __restrict__ lnd,
                                                    const float4* __restrict__ anch4,
                                                    int n, float* __restrict__ out) {
    __shared__ unsigned char sbuf[32768];     // keys (phase A) / supp matrix (phase B) / exact tmp
    __shared__ float4 sb4[M];
    __shared__ float  sar[M];
    __shared__ int    sidx[M];
    __shared__ short  ssel[MAX_OUT];
    __shared__ int    s_nsel;
    __shared__ unsigned s_ncall;

    const int t = threadIdx.x;

    // RACE-FREE snapshot + reset of g_ncand (one writer, barrier, uniform read)
    if (t == 0) { s_ncall = g_ncand; g_ncand = 0; }
    __syncthreads();
    unsigned nc_all = s_ncall;                // uniform across the block

    bool exact = (nc_all == 0u) || (nc_all > CAP);
    unsigned nc = (nc_all < M) ? nc_all : M;

    if (!exact) {
        // zero box working set (slots >= nc stay degenerate: IoU == 0)
        for (int k = t; k < M; k += 1024) {
            sb4[k] = make_float4(0.f, 0.f, 0.f, 0.f);
            sar[k] = 0.f; sidx[k] = 0;
        }
        unsigned long long* sk = (unsigned long long*)sbuf;
        unsigned ncr = (nc_all + 3u) & ~3u;
        for (int k = t; k < (int)ncr; k += 1024)
            sk[k] = (k < (int)nc_all) ? g_ckey[k] : 0ULL;
        __syncthreads();

        // rank-scatter: 4 threads per candidate, 256 candidates per pass.
        // WARP-UNIFORM: every thread executes every shfl (pad lanes use key 0 ->
        // no scatter). The base loop bound is block-uniform.
        for (int base = 0; base < (int)nc_all; base += 256) {
            int c = base + (t >> 2), h = t & 3;
            bool live = (c < (int)nc_all);
            unsigned long long mykey = live ? sk[c] : 0ULL;
            int r = 0;
            for (int j = h; j < (int)ncr; j += 4)
                r += (sk[j] > mykey) ? 1 : 0;
            r += __shfl_xor_sync(0xFFFFFFFFu, r, 1);   // all 32 lanes participate
            r += __shfl_xor_sync(0xFFFFFFFFu, r, 2);
            if (live && h == 0 && r < M) {             // ranks unique -> race-free scatter
                int idx = (int)(~(unsigned)(mykey & 0xFFFFFFFFull));
                sidx[r] = idx;
                float4 rg = __ldg(reg4 + idx);
                float4 an = __ldg(anch4 + idx);
                float y1, x1, y2, x2, ar;
                decode_box(rg, an, y1, x1, y2, x2, ar);
                sb4[r] = make_float4(y1, x1, y2, x2);
                sar[r] = ar;
            }
        }
        __syncthreads();

        // pairwise suppression matrix (reuse sbuf; keys no longer needed)
        unsigned* ssup = (unsigned*)sbuf;     // M x 16 words = 32KB
        for (int w = t; w < M * 16; w += 1024) {
            int i = w >> 4, ww = w & 15;
            float4 bi = sb4[i];
            float  ai = sar[i];
            unsigned word = 0;
#pragma unroll 8
            for (int jj = 0; jj < 32; jj++) {
                int j = (ww << 5) + jj;
                float4 bj = sb4[j];
                if (iou_f(bi.x, bi.y, bi.z, bi.w, ai, bj.x, bj.y, bj.z, bj.w, sar[j]) > NMS_TH)
                    word |= (1u << jj);
            }
            ssup[w] = word;
        }
        __syncthreads();

        // warp-serial greedy selection (warp 0: uniform loop conditions, full-mask ops)
        if (t < 32) {
            const unsigned FULL = 0xFFFFFFFFu;
            int lane = t;
            unsigned valid = 0;
            if (lane < 16) {
                int rem = (int)nc - lane * 32;
                valid = (rem >= 32) ? 0xFFFFFFFFu : ((rem <= 0) ? 0u : ((1u << rem) - 1u));
            }
            unsigned removed = 0;
            int nsel = 0;
            while (nsel < MAX_OUT) {
                unsigned alivew = valid & ~removed;
                unsigned bal = __ballot_sync(FULL, alivew != 0u);
                if (!bal) break;
                int src = __ffs(bal) - 1;
                unsigned w0 = __shfl_sync(FULL, alivew, src);
                int i = (src << 5) + __ffs(w0) - 1;
                if (lane == 0) ssel[nsel] = (short)i;
                unsigned supw = (lane < 16) ? ssup[(i << 4) + lane] : 0u;
                removed |= supw;                          // self bit removes i
                nsel++;
            }
            if (lane == 0) s_nsel = nsel;
        }
        __syncthreads();
        if (s_nsel >= MAX_OUT) {              // prefix of global greedy order -> exact result
            if (t < MAX_OUT)
                gather_one(t, sidx[ssel[t]], 1.f, reg4, lnd, anch4, out);
            return;
        }
        exact = true;                         // shortfall: tail below THRF may matter
        __syncthreads();
    }

    // ---- exact path (single block; correctness backstop, never taken on typical data) ----
    {
        float* red_s = (float*)sbuf;                    // 4KB
        int*   red_i = (int*)(sbuf + 4096);             // 4KB
        int*   f_idx = (int*)(sbuf + 8192);             // 800B
        int*   f_val = (int*)(sbuf + 8192 + 4 * MAX_OUT);
        for (int j = t; j < n; j += 1024) {
            float s = cls[j].y;
            g_scores[j] = (s > NMS_TH) ? s : -INFINITY;
        }
        __syncthreads();
        for (int it = 0; it < MAX_OUT; it++) {
            float best = -INFINITY; int bi = 0;
            for (int j = t; j < n; j += 1024) {
                float v = g_scores[j];
                if (v > best) { best = v; bi = j; }
            }
            red_s[t] = best; red_i[t] = bi;
            __syncthreads();
            for (int s = 512; s > 0; s >>= 1) {
                if (t < s) {
                    float vo = red_s[t + s]; int io = red_i[t + s];
                    if (vo > red_s[t] || (vo == red_s[t] && io < red_i[t])) {
                        red_s[t] = vo; red_i[t] = io;
                    }
                }
                __syncthreads();
            }
            int i = red_i[0];
            bool valid = (red_s[0] > -INFINITY);
            float4 rgi = __ldg(reg4 + i);
            float4 ani = __ldg(anch4 + i);
            float by1, bx1, by2, bx2, bar;
            decode_box(rgi, ani, by1, bx1, by2, bx2, bar);
            if (valid) {
                for (int j = t; j < n; j += 1024) {
                    if (g_scores[j] > -INFINITY) {
                        float4 rg = __ldg(reg4 + j);
                        float4 an = __ldg(anch4 + j);
                        float y1, x1, y2, x2, ar;
                        decode_box(rg, an, y1, x1, y2, x2, ar);
                        if (iou_f(y1, x1, y2, x2, ar, by1, bx1, by2, bx2, bar) > NMS_TH)
                            g_scores[j] = -INFINITY;
                    }
                }
            }
            if (t == 0) { f_idx[it] = i; f_val[it] = valid ? 1 : 0; }
            __syncthreads();
        }
        if (t < MAX_OUT)
            gather_one(t, f_val[t] ? f_idx[t] : 0, f_val[t] ? 1.f : 0.f, reg4, lnd, anch4, out);
    }
}

// ---------------- launch: TWO plain kernels ----------------
extern "C" void kernel_launch(void* const* d_in, const int* in_sizes, int n_in,
                              void* d_out, int out_size) {
    const float4* cls4  = (const float4*)d_in[0];
    const float4* reg4  = (const float4*)d_in[1];
    const float*  lnd   = (const float*)d_in[2];
    const float4* anch4 = (const float4*)d_in[3];

    int n = in_sizes[0] / 2;
    if (n > N_ANCH) n = N_ANCH;
    int nv = n >> 1;

    compact_kernel<<<(nv + 255) / 256, 256>>>(cls4, n);
    mega_kernel<<<1, 1024>>>((const float2*)cls4, reg4, lnd, anch4, n, (float*)d_out);
}

// round 11
// speedup vs baseline: 4.9482x; 4.9482x over previous
#include <cuda_runtime.h>
#include <math.h>

#define N_ANCH   172032
#define MAX_OUT  200
#define NMS_TH   0.4f
#define THRF     2.5f          // fixed compaction threshold; exactness-safe (prefix argument)
#define CAP      4096
#define M        512

// ---------------- static device scratch ----------------
__device__ unsigned g_ncand;             // BSS-zero; reset by greedy each run
__device__ unsigned g_nc;                // working-set size (written by rank blk0)
__device__ unsigned long long g_ckey[CAP];
__device__ float4   g_sb4[M];            // decoded sorted boxes (stale slots harmless, see greedy)
__device__ float    g_sar[M];
__device__ int      g_sidx[M];
__device__ unsigned g_supp[M * 16];      // 512x512 suppression bits
__device__ float    g_scores[N_ANCH];    // exact backstop only

// ---------------- decode helper (matches reference _decode) ----------------
__device__ __forceinline__ void decode_box(const float4& rg, const float4& an,
                                           float& y1, float& x1, float& y2, float& x2,
                                           float& ar) {
    float dx = rg.x * 0.1f, dy = rg.y * 0.1f, dw = rg.z * 0.2f, dh = rg.w * 0.2f;
    float xc = dx * an.z + an.x;
    float yc = dy * an.w + an.y;
    float w  = expf(dw) * an.z;
    float h  = expf(dh) * an.w;
    y1 = yc - 0.5f * h;  x1 = xc - 0.5f * w;
    y2 = yc + 0.5f * h;  x2 = xc + 0.5f * w;
    ar = (y2 - y1) * (x2 - x1);
}

__device__ __forceinline__ float iou_f(float ay1, float ax1, float ay2, float ax2, float aar,
                                       float by1, float bx1, float by2, float bx2, float bar) {
    float ih = fmaxf(fminf(ay2, by2) - fmaxf(ay1, by1), 0.f);
    float iw = fmaxf(fminf(ax2, bx2) - fmaxf(ax1, bx1), 0.f);
    float inter = ih * iw;
    return inter / (aar + bar - inter + 1e-12f);
}

__device__ __forceinline__ void gather_one(int t, int idx, float m,
                                           const float4* __restrict__ reg4,
                                           const float*  __restrict__ lnd,
                                           const float4* __restrict__ anch4,
                                           float* __restrict__ out) {
    float4 rg = __ldg(reg4 + idx);
    float4 an = __ldg(anch4 + idx);
    float y1, x1, y2, x2, ar;
    decode_box(rg, an, y1, x1, y2, x2, ar);
    out[4 * t + 0] = y1 * m;
    out[4 * t + 1] = x1 * m;
    out[4 * t + 2] = y2 * m;
    out[4 * t + 3] = x2 * m;
    const float* lp = lnd + 10 * idx;
    float* op = out + 4 * MAX_OUT + 10 * t;
#pragma unroll
    for (int k = 0; k < 5; k++) {
        float lx = lp[2 * k]     * 0.1f * an.z + an.x;
        float ly = lp[2 * k + 1] * 0.1f * an.w + an.y;
        op[2 * k]     = lx * m;
        op[2 * k + 1] = ly * m;
    }
}

// ---------------- 1) compact candidates above fixed threshold ----------------
__global__ void compact_kernel(const float4* __restrict__ cls4, int n) {
    int nv = n >> 1;                          // one float4 = two (cls0,score) pairs
    int v = blockIdx.x * blockDim.x + threadIdx.x;
    if (v < nv) {
        float4 c = __ldg(cls4 + v);
        if (c.y > THRF) {
            unsigned u = __float_as_uint(c.y) ^ 0x80000000u;
            unsigned pos = atomicAdd(&g_ncand, 1u);
            if (pos < CAP)
                g_ckey[pos] = ((unsigned long long)u << 32) | (unsigned)(~(unsigned)(2 * v));
        }
        if (c.w > THRF) {
            unsigned u = __float_as_uint(c.w) ^ 0x80000000u;
            unsigned pos = atomicAdd(&g_ncand, 1u);
            if (pos < CAP)
                g_ckey[pos] = ((unsigned long long)u << 32) | (unsigned)(~(unsigned)(2 * v + 1));
        }
    }
    if ((n & 1) && v == 0) {                  // generality guard (n is even here)
        float s = ((const float*)cls4)[2 * (n - 1) + 1];
        if (s > THRF) {
            unsigned u = __float_as_uint(s) ^ 0x80000000u;
            unsigned pos = atomicAdd(&g_ncand, 1u);
            if (pos < CAP)
                g_ckey[pos] = ((unsigned long long)u << 32) | (unsigned)(~(unsigned)(n - 1));
        }
    }
}

// ---------------- 2) rank-scatter sort + decode top-M (multi-SM) ----------------
__global__ __launch_bounds__(256) void rank_kernel(const float4* __restrict__ reg4,
                                                   const float4* __restrict__ anch4) {
    __shared__ unsigned long long sk[CAP];    // 32KB
    const int t = threadIdx.x;
    unsigned nc_all = g_ncand;
    if (blockIdx.x == 0 && t == 0)
        g_nc = (nc_all > CAP) ? 0u : ((nc_all < M) ? nc_all : M);   // overflow -> 0 -> exact path
    if (nc_all == 0u || nc_all > CAP) return;                        // uniform grid-wide
    if ((unsigned)(blockIdx.x * 64) >= nc_all) return;               // uniform per block

    unsigned ncr = (nc_all + 3u) & ~3u;
    for (int k = t; k < (int)ncr; k += 256)
        sk[k] = (k < (int)nc_all) ? g_ckey[k] : 0ULL;
    __syncthreads();

    // 4 threads per candidate; ALL threads execute every shfl (warp-uniform)
    int c = blockIdx.x * 64 + (t >> 2), h = t & 3;
    bool live = (c < (int)nc_all);
    unsigned long long mykey = live ? sk[c] : 0ULL;
    int r = 0;
    int j = h;
    for (; j + 12 < (int)ncr; j += 16) {      // 4 independent loads -> MLP hides LDS latency
        r += (sk[j]      > mykey) ? 1 : 0;
        r += (sk[j + 4]  > mykey) ? 1 : 0;
        r += (sk[j + 8]  > mykey) ? 1 : 0;
        r += (sk[j + 12] > mykey) ? 1 : 0;
    }
    for (; j < (int)ncr; j += 4)
        r += (sk[j] > mykey) ? 1 : 0;
    r += __shfl_xor_sync(0xFFFFFFFFu, r, 1);
    r += __shfl_xor_sync(0xFFFFFFFFu, r, 2);
    if (live && h == 0 && r < M) {            // ranks unique -> race-free scatter
        int idx = (int)(~(unsigned)(mykey & 0xFFFFFFFFull));
        g_sidx[r] = idx;
        float4 rg = __ldg(reg4 + idx);
        float4 an = __ldg(anch4 + idx);
        float y1, x1, y2, x2, ar;
        decode_box(rg, an, y1, x1, y2, x2, ar);
        g_sb4[r] = make_float4(y1, x1, y2, x2);
        g_sar[r] = ar;
    }
    // slots >= nc may hold stale data; harmless (greedy's valid mask ignores them)
}

// ---------------- 3) pairwise suppression bitmask (multi-SM) ----------------
__global__ __launch_bounds__(256) void pairs_kernel() {
    __shared__ float4 sb[M];                  // 8KB
    __shared__ float  sa[M];                  // 2KB
    const int t = threadIdx.x;
    for (int k = t; k < M; k += 256) { sb[k] = g_sb4[k]; sa[k] = g_sar[k]; }
    __syncthreads();
    int gid = blockIdx.x * 256 + t;           // M*16 = 8192 words over 32 blocks
    int i = gid >> 4, w = gid & 15;
    float4 bi = sb[i];
    float  ai = sa[i];
    unsigned word = 0;
#pragma unroll 8
    for (int jj = 0; jj < 32; jj++) {
        int j = (w << 5) + jj;
        float4 bj = sb[j];
        if (iou_f(bi.x, bi.y, bi.z, bi.w, ai, bj.x, bj.y, bj.z, bj.w, sa[j]) > NMS_TH)
            word |= (1u << jj);
    }
    g_supp[(i << 4) + w] = word;
}

// ---------------- 4) greedy selection + gather (single block) ----------------
__global__ __launch_bounds__(256) void greedy_kernel(const float2* __restrict__ cls,
                                                     const float4* __restrict__ reg4,
                                                     const float*  __restrict__ lnd,
                                                     const float4* __restrict__ anch4,
                                                     int n, float* __restrict__ out) {
    __shared__ unsigned ssup[M * 16];         // 32KB
    __shared__ int      ssidx[M];
    __shared__ short    ssel[MAX_OUT];
    __shared__ int      s_nsel;
    __shared__ unsigned s_nc;
    const int t = threadIdx.x;

    if (t == 0) { s_nc = g_nc; g_ncand = 0; } // snapshot + replay reset (race-free: barrier next)
    {   // vectorized preload of suppression matrix + indices
        const uint4* gsup4 = (const uint4*)g_supp;
        uint4* ssup4 = (uint4*)ssup;
        for (int k = t; k < M * 4; k += 256) ssup4[k] = gsup4[k];
        for (int k = t; k < M; k += 256) ssidx[k] = g_sidx[k];
    }
    __syncthreads();
    unsigned nc = s_nc;

    if (t < 32) {                             // warp-serial greedy
        const unsigned FULL = 0xFFFFFFFFu;
        int lane = t;
        unsigned valid = 0;
        if (lane < 16) {
            int rem = (int)nc - lane * 32;
            valid = (rem >= 32) ? 0xFFFFFFFFu : ((rem <= 0) ? 0u : ((1u << rem) - 1u));
        }
        unsigned removed = 0;
        int nsel = 0;
        while (nsel < MAX_OUT) {
            unsigned alivew = valid & ~removed;
            unsigned bal = __ballot_sync(FULL, alivew != 0u);
            if (!bal) break;
            int src = __ffs(bal) - 1;
            unsigned w0 = __shfl_sync(FULL, alivew, src);
            int i = (src << 5) + __ffs(w0) - 1;
            if (lane == 0) ssel[nsel] = (short)i;
            unsigned supw = (lane < 16) ? ssup[(i << 4) + lane] : 0u;
            removed |= supw;                   // self bit removes i
            nsel++;
        }
        if (lane == 0) s_nsel = nsel;
    }
    __syncthreads();
    if (s_nsel >= MAX_OUT) {                  // prefix of global greedy order -> exact result
        if (t < MAX_OUT)
            gather_one(t, ssidx[ssel[t]], 1.f, reg4, lnd, anch4, out);
        return;
    }

    // ---- exact backstop (shortfall/overflow; never taken on typical data) ----
    {
        float* red_s = (float*)ssup;                    // reuse 32KB buffer
        int*   red_i = (int*)(ssup + 256);
        int*   f_idx = (int*)(ssup + 512);
        int*   f_val = (int*)(ssup + 512 + MAX_OUT);
        for (int j = t; j < n; j += 256) {
            float s = cls[j].y;
            g_scores[j] = (s > NMS_TH) ? s : -INFINITY;
        }
        __syncthreads();
        for (int it = 0; it < MAX_OUT; it++) {
            float best = -INFINITY; int bi = 0;
            for (int j = t; j < n; j += 256) {
                float v = g_scores[j];
                if (v > best) { best = v; bi = j; }
            }
            red_s[t] = best; red_i[t] = bi;
            __syncthreads();
            for (int s = 128; s > 0; s >>= 1) {
                if (t < s) {
                    float vo = red_s[t + s]; int io = red_i[t + s];
                    if (vo > red_s[t] || (vo == red_s[t] && io < red_i[t])) {
                        red_s[t] = vo; red_i[t] = io;
                    }
                }
                __syncthreads();
            }
            int i = red_i[0];
            bool valid = (red_s[0] > -INFINITY);
            float4 rgi = __ldg(reg4 + i);
            float4 ani = __ldg(anch4 + i);
            float by1, bx1, by2, bx2, bar;
            decode_box(rgi, ani, by1, bx1, by2, bx2, bar);
            if (valid) {
                for (int j = t; j < n; j += 256) {
                    if (g_scores[j] > -INFINITY) {
                        float4 rg = __ldg(reg4 + j);
                        float4 an = __ldg(anch4 + j);
                        float y1, x1, y2, x2, ar;
                        decode_box(rg, an, y1, x1, y2, x2, ar);
                        if (iou_f(y1, x1, y2, x2, ar, by1, bx1, by2, bx2, bar) > NMS_TH)
                            g_scores[j] = -INFINITY;
                    }
                }
            }
            if (t == 0) { f_idx[it] = i; f_val[it] = valid ? 1 : 0; }
            __syncthreads();
        }
        if (t < MAX_OUT)
            gather_one(t, f_val[t] ? f_idx[t] : 0, f_val[t] ? 1.f : 0.f, reg4, lnd, anch4, out);
    }
}

// ---------------- launch: FOUR plain kernels ----------------
extern "C" void kernel_launch(void* const* d_in, const int* in_sizes, int n_in,
                              void* d_out, int out_size) {
    const float4* cls4  = (const float4*)d_in[0];
    const float4* reg4  = (const float4*)d_in[1];
    const float*  lnd   = (const float*)d_in[2];
    const float4* anch4 = (const float4*)d_in[3];

    int n = in_sizes[0] / 2;
    if (n > N_ANCH) n = N_ANCH;
    int nv = n >> 1;

    compact_kernel<<<(nv + 255) / 256, 256>>>(cls4, n);
    rank_kernel<<<CAP / 64, 256>>>(reg4, anch4);
    pairs_kernel<<<M * 16 / 256, 256>>>();
    greedy_kernel<<<1, 256>>>((const float2*)cls4, reg4, lnd, anch4, n, (float*)d_out);
}

// round 12
// speedup vs baseline: 10.0350x; 2.0280x over previous
#include <cuda_runtime.h>
#include <math.h>

#define N_ANCH   172032
#define MAX_OUT  200
#define NMS_TH   0.4f
#define THRF     2.5f          // fixed compaction threshold; exactness-safe (prefix argument)
#define CAP      4096
#define M        512

// ---------------- static device scratch ----------------
__device__ unsigned g_ncand;             // BSS-zero; reset by greedy each run
__device__ unsigned g_nc;                // working-set size (written by rank blk0)
__device__ unsigned long long g_ckey[CAP];
__device__ float4   g_sb4[M];            // decoded sorted boxes (stale slots harmless)
__device__ float    g_sar[M];
__device__ int      g_sidx[M];
__device__ unsigned g_supp[M * 16];      // 512x512 suppression bits (symmetric)
__device__ float    g_scores[N_ANCH];    // exact backstop only

// ---------------- decode helper (matches reference _decode) ----------------
__device__ __forceinline__ void decode_box(const float4& rg, const float4& an,
                                           float& y1, float& x1, float& y2, float& x2,
                                           float& ar) {
    float dx = rg.x * 0.1f, dy = rg.y * 0.1f, dw = rg.z * 0.2f, dh = rg.w * 0.2f;
    float xc = dx * an.z + an.x;
    float yc = dy * an.w + an.y;
    float w  = expf(dw) * an.z;
    float h  = expf(dh) * an.w;
    y1 = yc - 0.5f * h;  x1 = xc - 0.5f * w;
    y2 = yc + 0.5f * h;  x2 = xc + 0.5f * w;
    ar = (y2 - y1) * (x2 - x1);
}

__device__ __forceinline__ float iou_f(float ay1, float ax1, float ay2, float ax2, float aar,
                                       float by1, float bx1, float by2, float bx2, float bar) {
    float ih = fmaxf(fminf(ay2, by2) - fmaxf(ay1, by1), 0.f);
    float iw = fmaxf(fminf(ax2, bx2) - fmaxf(ax1, bx1), 0.f);
    float inter = ih * iw;
    return inter / (aar + bar - inter + 1e-12f);
}

__device__ __forceinline__ void gather_one(int t, int idx, float m,
                                           const float4* __restrict__ reg4,
                                           const float*  __restrict__ lnd,
                                           const float4* __restrict__ anch4,
                                           float* __restrict__ out) {
    float4 rg = __ldg(reg4 + idx);
    float4 an = __ldg(anch4 + idx);
    float y1, x1, y2, x2, ar;
    decode_box(rg, an, y1, x1, y2, x2, ar);
    out[4 * t + 0] = y1 * m;
    out[4 * t + 1] = x1 * m;
    out[4 * t + 2] = y2 * m;
    out[4 * t + 3] = x2 * m;
    const float* lp = lnd + 10 * idx;
    float* op = out + 4 * MAX_OUT + 10 * t;
#pragma unroll
    for (int k = 0; k < 5; k++) {
        float lx = lp[2 * k]     * 0.1f * an.z + an.x;
        float ly = lp[2 * k + 1] * 0.1f * an.w + an.y;
        op[2 * k]     = lx * m;
        op[2 * k + 1] = ly * m;
    }
}

// ---------------- 1) compact candidates above fixed threshold ----------------
__global__ void compact_kernel(const float4* __restrict__ cls4, int n) {
    int nv = n >> 1;
    int v = blockIdx.x * blockDim.x + threadIdx.x;
    if (v < nv) {
        float4 c = __ldg(cls4 + v);
        if (c.y > THRF) {
            unsigned u = __float_as_uint(c.y) ^ 0x80000000u;
            unsigned pos = atomicAdd(&g_ncand, 1u);
            if (pos < CAP)
                g_ckey[pos] = ((unsigned long long)u << 32) | (unsigned)(~(unsigned)(2 * v));
        }
        if (c.w > THRF) {
            unsigned u = __float_as_uint(c.w) ^ 0x80000000u;
            unsigned pos = atomicAdd(&g_ncand, 1u);
            if (pos < CAP)
                g_ckey[pos] = ((unsigned long long)u << 32) | (unsigned)(~(unsigned)(2 * v + 1));
        }
    }
    if ((n & 1) && v == 0) {
        float s = ((const float*)cls4)[2 * (n - 1) + 1];
        if (s > THRF) {
            unsigned u = __float_as_uint(s) ^ 0x80000000u;
            unsigned pos = atomicAdd(&g_ncand, 1u);
            if (pos < CAP)
                g_ckey[pos] = ((unsigned long long)u << 32) | (unsigned)(~(unsigned)(n - 1));
        }
    }
}

// ---------------- 2) rank-scatter sort + decode top-M (multi-SM) ----------------
__global__ __launch_bounds__(256) void rank_kernel(const float4* __restrict__ reg4,
                                                   const float4* __restrict__ anch4) {
    __shared__ unsigned long long sk[CAP];
    const int t = threadIdx.x;
    unsigned nc_all = g_ncand;
    if (blockIdx.x == 0 && t == 0)
        g_nc = (nc_all > CAP) ? 0u : ((nc_all < M) ? nc_all : M);   // overflow -> exact path
    if (nc_all == 0u || nc_all > CAP) return;
    if ((unsigned)(blockIdx.x * 64) >= nc_all) return;

    unsigned ncr = (nc_all + 3u) & ~3u;
    for (int k = t; k < (int)ncr; k += 256)
        sk[k] = (k < (int)nc_all) ? g_ckey[k] : 0ULL;
    __syncthreads();

    int c = blockIdx.x * 64 + (t >> 2), h = t & 3;
    bool live = (c < (int)nc_all);
    unsigned long long mykey = live ? sk[c] : 0ULL;
    int r = 0;
    int j = h;
    for (; j + 12 < (int)ncr; j += 16) {
        r += (sk[j]      > mykey) ? 1 : 0;
        r += (sk[j + 4]  > mykey) ? 1 : 0;
        r += (sk[j + 8]  > mykey) ? 1 : 0;
        r += (sk[j + 12] > mykey) ? 1 : 0;
    }
    for (; j < (int)ncr; j += 4)
        r += (sk[j] > mykey) ? 1 : 0;
    r += __shfl_xor_sync(0xFFFFFFFFu, r, 1);
    r += __shfl_xor_sync(0xFFFFFFFFu, r, 2);
    if (live && h == 0 && r < M) {
        int idx = (int)(~(unsigned)(mykey & 0xFFFFFFFFull));
        g_sidx[r] = idx;
        float4 rg = __ldg(reg4 + idx);
        float4 an = __ldg(anch4 + idx);
        float y1, x1, y2, x2, ar;
        decode_box(rg, an, y1, x1, y2, x2, ar);
        g_sb4[r] = make_float4(y1, x1, y2, x2);
        g_sar[r] = ar;
    }
}

// ---------------- 3) pairwise suppression bitmask (multi-SM) ----------------
__global__ __launch_bounds__(256) void pairs_kernel() {
    __shared__ float4 sb[M];
    __shared__ float  sa[M];
    const int t = threadIdx.x;
    for (int k = t; k < M; k += 256) { sb[k] = g_sb4[k]; sa[k] = g_sar[k]; }
    __syncthreads();
    int gid = blockIdx.x * 256 + t;
    int i = gid >> 4, w = gid & 15;
    float4 bi = sb[i];
    float  ai = sa[i];
    unsigned word = 0;
#pragma unroll 8
    for (int jj = 0; jj < 32; jj++) {
        int j = (w << 5) + jj;
        float4 bj = sb[j];
        if (iou_f(bi.x, bi.y, bi.z, bi.w, ai, bj.x, bj.y, bj.z, bj.w, sa[j]) > NMS_TH)
            word |= (1u << jj);
    }
    g_supp[(i << 4) + w] = word;
}

// ---------------- 4) fixed-point greedy + gather (single block) ----------------
__device__ __forceinline__ unsigned lowmask(int w, int wi, int bi) {
    return (w < wi) ? 0xFFFFFFFFu : ((w == wi) ? ((1u << bi) - 1u) : 0u);
}

__global__ __launch_bounds__(256) void greedy_kernel(const float2* __restrict__ cls,
                                                     const float4* __restrict__ reg4,
                                                     const float*  __restrict__ lnd,
                                                     const float4* __restrict__ anch4,
                                                     int n, float* __restrict__ out) {
    __shared__ unsigned ssup[M * 16];         // 32KB suppression matrix
    __shared__ int      ssidx[M];
    __shared__ short    ssel[MAX_OUT];
    __shared__ unsigned s_sel[16], s_new[16], s_pref[16];
    __shared__ int      s_nsel;
    __shared__ unsigned s_nc;
    const int t = threadIdx.x;

    if (t == 0) { s_nc = g_nc; g_ncand = 0; }
    {   // vectorized preload
        const uint4* gsup4 = (const uint4*)g_supp;
        uint4* ssup4 = (uint4*)ssup;
        for (int k = t; k < M * 4; k += 256) ssup4[k] = gsup4[k];
        for (int k = t; k < M; k += 256) ssidx[k] = g_sidx[k];
    }
    if (t < 16) {                             // init sel = valid mask
        // placeholder; fixed after barrier once s_nc visible
    }
    __syncthreads();
    unsigned nc = s_nc;
    if (t < 16) {
        int rem = (int)nc - t * 32;
        s_sel[t] = (rem >= 32) ? 0xFFFFFFFFu : ((rem <= 0) ? 0u : ((1u << rem) - 1u));
    }
    __syncthreads();

    // ---- Jacobi fixed-point: sel[i] = valid[i] & !(OR_{j<i} supp[i][j] & sel[j]) ----
    int converged = 0;
    for (int iter = 0; iter < 24; iter++) {
#pragma unroll
        for (int p = 0; p < 2; p++) {
            int i = t + (p << 8);
            int wi = i >> 5, bi = i & 31;
            const uint4* r4 = (const uint4*)&ssup[i << 4];
            unsigned acc = 0;
#pragma unroll
            for (int q = 0; q < 4; q++) {
                uint4 rv = r4[q];
                int w0 = q << 2;
                acc |= rv.x & s_sel[w0]     & lowmask(w0,     wi, bi);
                acc |= rv.y & s_sel[w0 + 1] & lowmask(w0 + 1, wi, bi);
                acc |= rv.z & s_sel[w0 + 2] & lowmask(w0 + 2, wi, bi);
                acc |= rv.w & s_sel[w0 + 3] & lowmask(w0 + 3, wi, bi);
            }
            int nb = (i < (int)nc) && (acc == 0u);
            unsigned word = __ballot_sync(0xFFFFFFFFu, nb);   // all 32 lanes execute
            if ((t & 31) == 0) s_new[i >> 5] = word;
        }
        __syncthreads();                       // s_new complete
        int mydiff = 0;
        if (t < 16) {
            mydiff = (s_new[t] != s_sel[t]);
            s_sel[t] = s_new[t];
        }
        int changed = __syncthreads_or(mydiff);   // barrier + block-OR (uniform result)
        if (!changed) { converged = 1; break; }
    }

    int nsel;
    if (converged) {
        // ---- enumerate first MAX_OUT selected, in order (warp 0) ----
        if (t < 32) {
            unsigned w = (t < 16) ? s_sel[t] : 0u;
            int c = __popc(w);
            int inc = c;
#pragma unroll
            for (int d = 1; d < 32; d <<= 1) {
                int v = __shfl_up_sync(0xFFFFFFFFu, inc, d);
                if (t >= (unsigned)d) inc += v;
            }
            if (t < 16) s_pref[t] = inc - c;   // exclusive prefix
            if (t == 15) s_nsel = (inc > MAX_OUT) ? MAX_OUT : inc;
        }
        __syncthreads();
#pragma unroll
        for (int p = 0; p < 2; p++) {
            int i = t + (p << 8);
            unsigned w = s_sel[i >> 5];
            if ((w >> (i & 31)) & 1u) {
                int order = (int)s_pref[i >> 5] + __popc(w & ((1u << (i & 31)) - 1u));
                if (order < MAX_OUT) ssel[order] = (short)i;
            }
        }
        __syncthreads();
        nsel = s_nsel;
    } else {
        // ---- safety net: proven warp-serial greedy (uniform branch) ----
        if (t < 32) {
            const unsigned FULL = 0xFFFFFFFFu;
            int lane = t;
            unsigned valid = 0;
            if (lane < 16) {
                int rem = (int)nc - lane * 32;
                valid = (rem >= 32) ? 0xFFFFFFFFu : ((rem <= 0) ? 0u : ((1u << rem) - 1u));
            }
            unsigned removed = 0;
            int ns = 0;
            while (ns < MAX_OUT) {
                unsigned alivew = valid & ~removed;
                unsigned bal = __ballot_sync(FULL, alivew != 0u);
                if (!bal) break;
                int src = __ffs(bal) - 1;
                unsigned w0 = __shfl_sync(FULL, alivew, src);
                int i = (src << 5) + __ffs(w0) - 1;
                if (lane == 0) ssel[ns] = (short)i;
                unsigned supw = (lane < 16) ? ssup[(i << 4) + lane] : 0u;
                removed |= supw;
                ns++;
            }
            if (lane == 0) s_nsel = ns;
        }
        __syncthreads();
        nsel = s_nsel;
    }

    if (nsel >= MAX_OUT) {                    // exact greedy prefix -> done
        if (t < MAX_OUT)
            gather_one(t, ssidx[ssel[t]], 1.f, reg4, lnd, anch4, out);
        return;
    }

    // ---- exact backstop (shortfall/overflow; not taken on typical data) ----
    {
        float* red_s = (float*)ssup;
        int*   red_i = (int*)(ssup + 256);
        int*   f_idx = (int*)(ssup + 512);
        int*   f_val = (int*)(ssup + 512 + MAX_OUT);
        for (int j = t; j < n; j += 256) {
            float s = cls[j].y;
            g_scores[j] = (s > NMS_TH) ? s : -INFINITY;
        }
        __syncthreads();
        for (int it = 0; it < MAX_OUT; it++) {
            float best = -INFINITY; int bi = 0;
            for (int j = t; j < n; j += 256) {
                float v = g_scores[j];
                if (v > best) { best = v; bi = j; }
            }
            red_s[t] = best; red_i[t] = bi;
            __syncthreads();
            for (int s = 128; s > 0; s >>= 1) {
                if (t < s) {
                    float vo = red_s[t + s]; int io = red_i[t + s];
                    if (vo > red_s[t] || (vo == red_s[t] && io < red_i[t])) {
                        red_s[t] = vo; red_i[t] = io;
                    }
                }
                __syncthreads();
            }
            int i = red_i[0];
            bool valid = (red_s[0] > -INFINITY);
            float4 rgi = __ldg(reg4 + i);
            float4 ani = __ldg(anch4 + i);
            float by1, bx1, by2, bx2, bar;
            decode_box(rgi, ani, by1, bx1, by2, bx2, bar);
            if (valid) {
                for (int j = t; j < n; j += 256) {
                    if (g_scores[j] > -INFINITY) {
                        float4 rg = __ldg(reg4 + j);
                        float4 an = __ldg(anch4 + j);
                        float y1, x1, y2, x2, ar;
                        decode_box(rg, an, y1, x1, y2, x2, ar);
                        if (iou_f(y1, x1, y2, x2, ar, by1, bx1, by2, bx2, bar) > NMS_TH)
                            g_scores[j] = -INFINITY;
                    }
                }
            }
            if (t == 0) { f_idx[it] = i; f_val[it] = valid ? 1 : 0; }
            __syncthreads();
        }
        if (t < MAX_OUT)
            gather_one(t, f_val[t] ? f_idx[t] : 0, f_val[t] ? 1.f : 0.f, reg4, lnd, anch4, out);
    }
}

// ---------------- launch: FOUR plain kernels ----------------
extern "C" void kernel_launch(void* const* d_in, const int* in_sizes, int n_in,
                              void* d_out, int out_size) {
    const float4* cls4  = (const float4*)d_in[0];
    const float4* reg4  = (const float4*)d_in[1];
    const float*  lnd   = (const float*)d_in[2];
    const float4* anch4 = (const float4*)d_in[3];

    int n = in_sizes[0] / 2;
    if (n > N_ANCH) n = N_ANCH;
    int nv = n >> 1;

    compact_kernel<<<(nv + 255) / 256, 256>>>(cls4, n);
    rank_kernel<<<CAP / 64, 256>>>(reg4, anch4);
    pairs_kernel<<<M * 16 / 256, 256>>>();
    greedy_kernel<<<1, 256>>>((const float2*)cls4, reg4, lnd, anch4, n, (float*)d_out);
}